// round 2
// baseline (speedup 1.0000x reference)
#include <cuda_runtime.h>
#include <math.h>
#include <math_constants.h>

#define BATCH 16
#define TLEN  2048
#define HDIM  64
#define DDIM  512
#define MTOT  (BATCH * TLEN)

// Scratch: h stored transposed [HDIM][MTOT] so the GEMM A-tile load is k-major
// and fully coalesced with conflict-free shared stores.
__device__ float g_h[HDIM * (size_t)MTOT];

__device__ __forceinline__ float mass_from_sum(float sE, float sx, float sy, float sz) {
    float s2 = sx * sx + sy * sy + sz * sz;
    float m2 = sE * sE - s2;
    m2 = fmaxf(m2, 0.0f);
    return sqrtf(m2 + 1e-8f);
}

// ---------------------------------------------------------------------------
// Kernel A: per-token top-8 Minkowski neighbors -> masses (k=2,4,8) -> h=gelu(mass@W1+b1)
// Grid: (TLEN/256, BATCH), 256 threads. One batch's P[2048][4] staged in SMEM.
// ---------------------------------------------------------------------------
__global__ __launch_bounds__(256) void mass_h_kernel(
    const float* __restrict__ tok,     // [B,T,4]
    const void*  __restrict__ maskp,   // [B,T] bool — dtype unknown (u8 / i32 / f32)
    const float* __restrict__ W1,      // [3,64]
    const float* __restrict__ b1)      // [64]
{
    __shared__ float4 sP[TLEN];
    __shared__ int sLen;

    const int b   = blockIdx.y;
    const int tid = threadIdx.x;
    if (tid == 0) sLen = 0;
    __syncthreads();

    // --- dtype-agnostic mask length: mask[b][0] is always true, so word 0 of
    // the buffer discriminates the element width.
    const unsigned int w0 = *(const unsigned int*)maskp;
    const bool byte_mode = (w0 == 0x01010101u) || (w0 == 0xFFFFFFFFu);

    // Build P = (E, px, py, pz) in shared; count valid tokens (mask is a prefix).
    int cnt = 0;
    #pragma unroll
    for (int s = tid; s < TLEN; s += 256) {
        float4 c = ((const float4*)tok)[b * TLEN + s];
        float E = c.x, Pt = c.y, eta = c.z, phi = c.w;
        float sphi, cphi;
        sincosf(phi, &sphi, &cphi);
        float px = Pt * cphi;
        float py = Pt * sphi;
        eta = fminf(fmaxf(eta, -20.0f), 20.0f);
        float pz = Pt * sinhf(eta);
        sP[s] = make_float4(E, px, py, pz);
        if (byte_mode) {
            cnt += (((const unsigned char*)maskp)[b * TLEN + s] != 0) ? 1 : 0;
        } else {
            cnt += (((const unsigned int*)maskp)[b * TLEN + s] != 0u) ? 1 : 0;
        }
    }
    #pragma unroll
    for (int o = 16; o > 0; o >>= 1) cnt += __shfl_down_sync(0xffffffffu, cnt, o);
    if ((tid & 31) == 0) atomicAdd(&sLen, cnt);
    __syncthreads();

    const int L = sLen;
    const int t = blockIdx.x * 256 + tid;

    float mass0, mass1, mass2;

    if (t < L) {
        float4 q = sP[t];
        const float qE = q.x, qx = -q.y, qy = -q.z, qz = -q.w;

        float v[8];
        int   ix[8];
        #pragma unroll
        for (int j = 0; j < 8; j++) { v[j] = -CUDART_INF_F; ix[j] = 0x7fffffff; }

        for (int s = 0; s < L; s++) {
            float4 p = sP[s];
            float d = fmaf(qz, p.w, fmaf(qy, p.z, fmaf(qx, p.y, qE * p.x)));
            if (d > v[7]) {
                float nv = d; int ni = s;
                #pragma unroll
                for (int j = 0; j < 8; j++) {
                    // stable insertion: ties ordered by ascending original index,
                    // in both the insert phase and the shift phase.
                    bool sw = (nv > v[j]) || (nv == v[j] && ni < ix[j]);
                    float tv = sw ? v[j] : nv;
                    v[j]     = sw ? nv   : v[j];
                    nv = tv;
                    int ti = sw ? ix[j] : ni;
                    ix[j]  = sw ? ni    : ix[j];
                    ni = ti;
                }
            }
        }

        // Cumulative sums in descending-dot order (matches reference cumsum fp order).
        float sE = 0.f, sx = 0.f, sy = 0.f, sz = 0.f;
        mass0 = mass1 = mass2 = 0.f;
        #pragma unroll
        for (int j = 0; j < 8; j++) {
            float4 p = sP[ix[j]];
            sE += p.x; sx += p.y; sy += p.z; sz += p.w;
            if (j == 1) mass0 = mass_from_sum(sE, sx, sy, sz);
            if (j == 3) mass1 = mass_from_sum(sE, sx, sy, sz);
            if (j == 7) mass2 = mass_from_sum(sE, sx, sy, sz);
        }
    } else {
        // masked token: m2 * 0 -> sqrt(1e-8), exactly as the reference computes it
        float mm = sqrtf(1e-8f);
        mass0 = mass1 = mass2 = mm;
    }

    // h = gelu(mass @ W1 + b1), stored transposed: g_h[c][m]
    const int m = b * TLEN + t;
    #pragma unroll 8
    for (int c = 0; c < HDIM; c++) {
        float x = fmaf(mass0, __ldg(&W1[c]),
                  fmaf(mass1, __ldg(&W1[HDIM + c]),
                  fmaf(mass2, __ldg(&W1[2 * HDIM + c]), __ldg(&b1[c]))));
        float g = x * 0.5f * (1.0f + erff(x * 0.70710678118654752f));
        g_h[(size_t)c * MTOT + m] = g;
    }
}

// ---------------------------------------------------------------------------
// Kernel B: out[M,512] = h[M,64] @ W2[64,512] + b2
// Block tile 128(M) x 64(N), K=64 loaded once. 256 threads, 8x4 microtile.
// Shared: As[64][128] (32KB) + Bs[64][64] (16KB) = 48KB exactly.
// ---------------------------------------------------------------------------
__global__ __launch_bounds__(256) void mlp2_kernel(
    const float* __restrict__ W2,   // [64,512]
    const float* __restrict__ b2,   // [512]
    float* __restrict__ out)        // [M,512]
{
    __shared__ float As[64][128];
    __shared__ float Bs[64][64];

    const int m0  = blockIdx.x * 128;
    const int n0  = blockIdx.y * 64;
    const int tid = threadIdx.x;

    // Load A tile: g_h is [64][MTOT] k-major -> direct coalesced float4 loads.
    #pragma unroll
    for (int i = 0; i < 8; i++) {
        int f  = tid + 256 * i;       // 0..2047
        int k  = f >> 5;              // 64 rows
        int mq = f & 31;              // 32 float4 per row
        float4 vA = *(const float4*)&g_h[(size_t)k * MTOT + m0 + mq * 4];
        *(float4*)&As[k][mq * 4] = vA;
    }
    // Load B tile: W2[k][n0 .. n0+63]
    #pragma unroll
    for (int i = 0; i < 4; i++) {
        int f  = tid + 256 * i;       // 0..1023
        int k  = f >> 4;
        int nq = f & 15;
        float4 vB = *(const float4*)&W2[k * DDIM + n0 + nq * 4];
        *(float4*)&Bs[k][nq * 4] = vB;
    }
    __syncthreads();

    const int rm = (tid & 15) * 8;
    const int rn = (tid >> 4) * 4;

    float acc[8][4];
    #pragma unroll
    for (int i = 0; i < 8; i++)
        #pragma unroll
        for (int j = 0; j < 4; j++) acc[i][j] = 0.0f;

    #pragma unroll 16
    for (int k = 0; k < 64; k++) {
        float4 a0 = *(float4*)&As[k][rm];
        float4 a1 = *(float4*)&As[k][rm + 4];
        float4 bb = *(float4*)&Bs[k][rn];
        float a[8] = {a0.x, a0.y, a0.z, a0.w, a1.x, a1.y, a1.z, a1.w};
        float bv[4] = {bb.x, bb.y, bb.z, bb.w};
        #pragma unroll
        for (int i = 0; i < 8; i++)
            #pragma unroll
            for (int j = 0; j < 4; j++)
                acc[i][j] = fmaf(a[i], bv[j], acc[i][j]);
    }

    float4 bias = *(const float4*)&b2[n0 + rn];
    #pragma unroll
    for (int i = 0; i < 8; i++) {
        float4 o;
        o.x = acc[i][0] + bias.x;
        o.y = acc[i][1] + bias.y;
        o.z = acc[i][2] + bias.z;
        o.w = acc[i][3] + bias.w;
        *(float4*)&out[(size_t)(m0 + rm + i) * DDIM + n0 + rn] = o;
    }
}

// ---------------------------------------------------------------------------
extern "C" void kernel_launch(void* const* d_in, const int* in_sizes, int n_in,
                              void* d_out, int out_size) {
    const float* tok  = (const float*)d_in[0];   // [16,2048,4]
    const void*  mask = (const void*)d_in[1];    // [16,2048] bool (dtype probed in-kernel)
    const float* W1   = (const float*)d_in[2];   // [3,64]
    const float* b1   = (const float*)d_in[3];   // [64]
    const float* W2   = (const float*)d_in[4];   // [64,512]
    const float* b2   = (const float*)d_in[5];   // [512]
    float*       out  = (float*)d_out;           // [16,2048,512]

    dim3 gA(TLEN / 256, BATCH);
    mass_h_kernel<<<gA, 256>>>(tok, mask, W1, b1);

    dim3 gB(MTOT / 128, DDIM / 64);
    mlp2_kernel<<<gB, 256>>>(W2, b2, out);
}

// round 3
// speedup vs baseline: 1.3244x; 1.3244x over previous
#include <cuda_runtime.h>
#include <math.h>
#include <math_constants.h>

#define BATCH 16
#define TLEN  2048
#define HDIM  64
#define DDIM  512
#define MTOT  (BATCH * TLEN)

// h stored transposed [HDIM][MTOT]: k-major for the GEMM A-tile loads.
__device__ float g_h[HDIM * (size_t)MTOT];

__device__ __forceinline__ float mass_from_sum(float sE, float sx, float sy, float sz) {
    float s2 = sx * sx + sy * sy + sz * sz;
    float m2 = sE * sE - s2;
    m2 = fmaxf(m2, 0.0f);
    return sqrtf(m2 + 1e-8f);
}

// ---- packed fp32x2 helpers (Blackwell) ----
__device__ __forceinline__ unsigned long long pk2(float x, float y) {
    unsigned long long r;
    asm("mov.b64 %0, {%1, %2};" : "=l"(r) : "f"(x), "f"(y));
    return r;
}
__device__ __forceinline__ void upk2(unsigned long long a, float& x, float& y) {
    asm("mov.b64 {%0, %1}, %2;" : "=f"(x), "=f"(y) : "l"(a));
}
__device__ __forceinline__ void ffma2(unsigned long long& acc, unsigned long long a, unsigned long long b) {
    asm("fma.rn.f32x2 %0, %1, %2, %0;" : "+l"(acc) : "l"(a), "l"(b));
}

// ---------------------------------------------------------------------------
// Kernel A: 4 lanes cooperate per token. Each lane scans s = r, r+4, ... < L,
// keeps a stable private top-8, then a shuffle merge yields the global top-8
// in exact lax.top_k order. Masses at prefix 2/4/8 -> h = gelu(mass@W1+b1).
// Grid: (TLEN/64, BATCH), 256 threads (64 tokens per block).
// ---------------------------------------------------------------------------
__global__ __launch_bounds__(256) void mass_h_kernel(
    const float* __restrict__ tok,     // [B,T,4]
    const void*  __restrict__ maskp,   // [B,T] bool — dtype probed (u8 / 32-bit)
    const float* __restrict__ W1,      // [3,64]
    const float* __restrict__ b1)      // [64]
{
    __shared__ float4 sP[TLEN];
    __shared__ int sLen;

    const int b   = blockIdx.y;
    const int tid = threadIdx.x;
    if (tid == 0) sLen = 0;
    __syncthreads();

    // mask[0][0] is always true -> first word discriminates element width.
    const unsigned int w0 = *(const unsigned int*)maskp;
    const bool byte_mode = (w0 == 0x01010101u) || (w0 == 0xFFFFFFFFu);

    int cnt = 0;
    #pragma unroll
    for (int s = tid; s < TLEN; s += 256) {
        float4 c = ((const float4*)tok)[b * TLEN + s];
        float E = c.x, Pt = c.y, eta = c.z, phi = c.w;
        float sphi, cphi;
        sincosf(phi, &sphi, &cphi);
        float px = Pt * cphi;
        float py = Pt * sphi;
        eta = fminf(fmaxf(eta, -20.0f), 20.0f);
        float pz = Pt * sinhf(eta);
        sP[s] = make_float4(E, px, py, pz);
        if (byte_mode)
            cnt += (((const unsigned char*)maskp)[b * TLEN + s] != 0) ? 1 : 0;
        else
            cnt += (((const unsigned int*)maskp)[b * TLEN + s] != 0u) ? 1 : 0;
    }
    #pragma unroll
    for (int o = 16; o > 0; o >>= 1) cnt += __shfl_down_sync(0xffffffffu, cnt, o);
    if ((tid & 31) == 0) atomicAdd(&sLen, cnt);
    __syncthreads();

    const int L    = sLen;
    const int r    = tid & 3;                       // lane within token group
    const int t    = blockIdx.x * 64 + (tid >> 2);  // token
    const int lane = tid & 31;
    const unsigned gmask = 0xFu << (lane & ~3);

    float mass0, mass1, mass2;

    if (t < L) {
        float4 q = sP[t];
        const float qE = q.x, qx = -q.y, qy = -q.z, qz = -q.w;

        float v[8];
        int   ix[8];
        #pragma unroll
        for (int j = 0; j < 8; j++) { v[j] = -CUDART_INF_F; ix[j] = 0x7fffffff; }

        // Private scan over s = r, r+4, ...  (ascending -> within-lane stability;
        // d == v[7] safely dropped: 8 same-lane entries already beat it).
        #pragma unroll 4
        for (int s = r; s < L; s += 4) {
            float4 p = sP[s];
            float d = fmaf(qz, p.w, fmaf(qy, p.z, fmaf(qx, p.y, qE * p.x)));
            if (d > v[7]) {
                float nv = d; int ni = s;
                #pragma unroll
                for (int j = 0; j < 8; j++) {
                    bool sw = (nv > v[j]) || (nv == v[j] && ni < ix[j]);
                    float tv = sw ? v[j] : nv;
                    v[j]     = sw ? nv   : v[j];
                    nv = tv;
                    int ti = sw ? ix[j] : ni;
                    ix[j]  = sw ? ni    : ix[j];
                    ni = ti;
                }
            }
        }

        // Merge 4 sorted lists: 8 rounds of group-max (value desc, index asc).
        float sE = 0.f, sx = 0.f, sy = 0.f, sz = 0.f;
        mass0 = mass1 = mass2 = 0.f;
        #pragma unroll
        for (int j = 0; j < 8; j++) {
            float wv = v[0];
            int   wi = ix[0];
            #pragma unroll
            for (int off = 1; off <= 2; off <<= 1) {
                float ov = __shfl_xor_sync(gmask, wv, off);
                int   oi = __shfl_xor_sync(gmask, wi, off);
                bool take = (ov > wv) || (ov == wv && oi < wi);
                wv = take ? ov : wv;
                wi = take ? oi : wi;
            }
            bool won = (ix[0] == wi);
            #pragma unroll
            for (int u = 0; u < 7; u++) {
                v[u]  = won ? v[u + 1]  : v[u];
                ix[u] = won ? ix[u + 1] : ix[u];
            }
            if (won) { v[7] = -CUDART_INF_F; ix[7] = 0x7fffffff; }

            float4 p = sP[wi];
            sE += p.x; sx += p.y; sy += p.z; sz += p.w;
            if (j == 1) mass0 = mass_from_sum(sE, sx, sy, sz);
            if (j == 3) mass1 = mass_from_sum(sE, sx, sy, sz);
            if (j == 7) mass2 = mass_from_sum(sE, sx, sy, sz);
        }
    } else {
        float mm = sqrtf(1e-8f);  // m2 * 0 -> sqrt(1e-8), as the reference
        mass0 = mass1 = mass2 = mm;
    }

    // h = gelu(mass @ W1 + b1); each of the 4 lanes writes 16 of 64 channels.
    const int m = b * TLEN + t;
    #pragma unroll
    for (int cc = 0; cc < 16; cc++) {
        int c = r * 16 + cc;
        float x = fmaf(mass0, __ldg(&W1[c]),
                  fmaf(mass1, __ldg(&W1[HDIM + c]),
                  fmaf(mass2, __ldg(&W1[2 * HDIM + c]), __ldg(&b1[c]))));
        float g = x * 0.5f * (1.0f + erff(x * 0.70710678118654752f));
        g_h[(size_t)c * MTOT + m] = g;
    }
}

// ---------------------------------------------------------------------------
// Kernel B: out[M,512] = h[M,64] @ W2[64,512] + b2
// 64x64 tile, 64 threads, 8x8 microtile, packed fma.rn.f32x2.
// Shared: As[64][64] + Bs[64][64] = 32KB -> ~7 blocks/SM.
// ---------------------------------------------------------------------------
__global__ __launch_bounds__(64) void mlp2_kernel(
    const float* __restrict__ W2,   // [64,512]
    const float* __restrict__ b2,   // [512]
    float* __restrict__ out)        // [M,512]
{
    __shared__ float As[64][64];
    __shared__ float Bs[64][64];

    const int m0  = blockIdx.x * 64;
    const int n0  = blockIdx.y * 64;
    const int tid = threadIdx.x;

    // A tile: g_h k-major -> coalesced float4 loads. 1024 float4 / 64 threads.
    #pragma unroll
    for (int i = 0; i < 16; i++) {
        int f  = tid + 64 * i;        // 0..1023
        int k  = f >> 4;
        int mq = f & 15;
        *(float4*)&As[k][mq * 4] = *(const float4*)&g_h[(size_t)k * MTOT + m0 + mq * 4];
    }
    // B tile: W2[k][n0 .. n0+63]
    #pragma unroll
    for (int i = 0; i < 16; i++) {
        int f  = tid + 64 * i;
        int k  = f >> 4;
        int nq = f & 15;
        *(float4*)&Bs[k][nq * 4] = *(const float4*)&W2[k * DDIM + n0 + nq * 4];
    }
    __syncthreads();

    const int rm = (tid & 7) * 8;
    const int rn = (tid >> 3) * 8;

    unsigned long long acc[8][4];
    #pragma unroll
    for (int i = 0; i < 8; i++)
        #pragma unroll
        for (int j = 0; j < 4; j++) acc[i][j] = 0ULL;  // (0.0f, 0.0f)

    #pragma unroll 8
    for (int k = 0; k < 64; k++) {
        float4 a0 = *(float4*)&As[k][rm];
        float4 a1 = *(float4*)&As[k][rm + 4];
        float4 c0 = *(float4*)&Bs[k][rn];
        float4 c1 = *(float4*)&Bs[k][rn + 4];
        unsigned long long bp0 = pk2(c0.x, c0.y);
        unsigned long long bp1 = pk2(c0.z, c0.w);
        unsigned long long bp2 = pk2(c1.x, c1.y);
        unsigned long long bp3 = pk2(c1.z, c1.w);
        float av[8] = {a0.x, a0.y, a0.z, a0.w, a1.x, a1.y, a1.z, a1.w};
        #pragma unroll
        for (int i = 0; i < 8; i++) {
            unsigned long long ad = pk2(av[i], av[i]);
            ffma2(acc[i][0], ad, bp0);
            ffma2(acc[i][1], ad, bp1);
            ffma2(acc[i][2], ad, bp2);
            ffma2(acc[i][3], ad, bp3);
        }
    }

    float4 bias0 = *(const float4*)&b2[n0 + rn];
    float4 bias1 = *(const float4*)&b2[n0 + rn + 4];
    #pragma unroll
    for (int i = 0; i < 8; i++) {
        float x0, y0, x1, y1, x2, y2, x3, y3;
        upk2(acc[i][0], x0, y0);
        upk2(acc[i][1], x1, y1);
        upk2(acc[i][2], x2, y2);
        upk2(acc[i][3], x3, y3);
        float4 o0 = make_float4(x0 + bias0.x, y0 + bias0.y, x1 + bias0.z, y1 + bias0.w);
        float4 o1 = make_float4(x2 + bias1.x, y2 + bias1.y, x3 + bias1.z, y3 + bias1.w);
        float* row = &out[(size_t)(m0 + rm + i) * DDIM + n0 + rn];
        *(float4*)row       = o0;
        *(float4*)(row + 4) = o1;
    }
}

// ---------------------------------------------------------------------------
extern "C" void kernel_launch(void* const* d_in, const int* in_sizes, int n_in,
                              void* d_out, int out_size) {
    const float* tok  = (const float*)d_in[0];   // [16,2048,4]
    const void*  mask = (const void*)d_in[1];    // [16,2048] bool (dtype probed)
    const float* W1   = (const float*)d_in[2];   // [3,64]
    const float* b1   = (const float*)d_in[3];   // [64]
    const float* W2   = (const float*)d_in[4];   // [64,512]
    const float* b2   = (const float*)d_in[5];   // [512]
    float*       out  = (float*)d_out;           // [16,2048,512]

    dim3 gA(TLEN / 64, BATCH);
    mass_h_kernel<<<gA, 256>>>(tok, mask, W1, b1);

    dim3 gB(MTOT / 64, DDIM / 64);
    mlp2_kernel<<<gB, 64>>>(W2, b2, out);
}

// round 4
// speedup vs baseline: 1.8983x; 1.4334x over previous
#include <cuda_runtime.h>
#include <math.h>
#include <math_constants.h>

#define BATCH 16
#define TLEN  2048
#define HDIM  64
#define DDIM  512
#define MTOT  (BATCH * TLEN)

// h stored transposed [HDIM][MTOT]: k-major for the GEMM A-tile loads.
__device__ float g_h[HDIM * (size_t)MTOT];

__device__ __forceinline__ float mass_from_sum(float sE, float sx, float sy, float sz) {
    float s2 = sx * sx + sy * sy + sz * sz;
    float m2 = sE * sE - s2;
    m2 = fmaxf(m2, 0.0f);
    return sqrtf(m2 + 1e-8f);
}

// ---- packed fp32x2 helpers (Blackwell) ----
__device__ __forceinline__ unsigned long long pk2(float x, float y) {
    unsigned long long r;
    asm("mov.b64 %0, {%1, %2};" : "=l"(r) : "f"(x), "f"(y));
    return r;
}
__device__ __forceinline__ void upk2(unsigned long long a, float& x, float& y) {
    asm("mov.b64 {%0, %1}, %2;" : "=f"(x), "=f"(y) : "l"(a));
}
__device__ __forceinline__ void ffma2(unsigned long long& acc, unsigned long long a, unsigned long long b) {
    asm("fma.rn.f32x2 %0, %1, %2, %0;" : "+l"(acc) : "l"(a), "l"(b));
}

// ---------------------------------------------------------------------------
// Kernel A: 2 lanes per token. Lane r scans s = r, r+2, ... < L ascending,
// keeping a private top-8 via a cheap compare-exchange cascade (strict > at
// every level == exact lax.top_k tie order, since per-lane scan is ascending).
// Then an 8-round pairwise shuffle merge (value desc, index asc) yields the
// global top-8 order; prefix sums at 2/4/8 -> masses -> h = gelu(mass@W1+b1).
// Grid: (TLEN/128, BATCH), 256 threads (128 tokens per block).
// ---------------------------------------------------------------------------
__global__ __launch_bounds__(256) void mass_h_kernel(
    const float* __restrict__ tok,     // [B,T,4]
    const void*  __restrict__ maskp,   // [B,T] bool — dtype probed (u8 / 32-bit)
    const float* __restrict__ W1,      // [3,64]
    const float* __restrict__ b1)      // [64]
{
    __shared__ float4 sP[TLEN];
    __shared__ int sLen;

    const int b   = blockIdx.y;
    const int tid = threadIdx.x;
    if (tid == 0) sLen = 0;
    __syncthreads();

    // mask[0][0] is always true -> first word discriminates element width.
    const unsigned int w0 = *(const unsigned int*)maskp;
    const bool byte_mode = (w0 == 0x01010101u) || (w0 == 0xFFFFFFFFu);

    int cnt = 0;
    #pragma unroll
    for (int s = tid; s < TLEN; s += 256) {
        float4 c = ((const float4*)tok)[b * TLEN + s];
        float E = c.x, Pt = c.y, eta = c.z, phi = c.w;
        float sphi, cphi;
        sincosf(phi, &sphi, &cphi);
        float px = Pt * cphi;
        float py = Pt * sphi;
        eta = fminf(fmaxf(eta, -20.0f), 20.0f);
        float pz = Pt * sinhf(eta);
        sP[s] = make_float4(E, px, py, pz);
        if (byte_mode)
            cnt += (((const unsigned char*)maskp)[b * TLEN + s] != 0) ? 1 : 0;
        else
            cnt += (((const unsigned int*)maskp)[b * TLEN + s] != 0u) ? 1 : 0;
    }
    #pragma unroll
    for (int o = 16; o > 0; o >>= 1) cnt += __shfl_down_sync(0xffffffffu, cnt, o);
    if ((tid & 31) == 0) atomicAdd(&sLen, cnt);
    __syncthreads();

    const int L = sLen;
    const int r = tid & 1;                        // lane within token pair
    const int t = blockIdx.x * 128 + (tid >> 1);  // token

    float mass0, mass1, mass2;

    if (t < L) {
        float4 q = sP[t];
        const float qE = q.x, qx = -q.y, qy = -q.z, qz = -q.w;

        float v[8];
        int   ix[8];
        #pragma unroll
        for (int j = 0; j < 8; j++) { v[j] = -CUDART_INF_F; ix[j] = 0x7fffffff; }

        // Ascending private scan; strict-> cascade preserves lax.top_k tie order.
        #pragma unroll 4
        for (int s = r; s < L; s += 2) {
            float4 p = sP[s];
            float d = fmaf(qz, p.w, fmaf(qy, p.z, fmaf(qx, p.y, qE * p.x)));
            if (d > v[7]) {
                float nv = d; int ni = s;
                #pragma unroll
                for (int j = 0; j < 8; j++) {
                    bool sw   = nv > v[j];
                    float hi  = fmaxf(nv, v[j]);
                    float lo  = fminf(nv, v[j]);
                    int hidx  = sw ? ni    : ix[j];
                    int lidx  = sw ? ix[j] : ni;
                    v[j] = hi; ix[j] = hidx;
                    nv   = lo; ni    = lidx;
                }
            }
        }

        // Merge the two sorted 8-lists: 8 rounds of pair-max (value desc, index asc).
        float sE = 0.f, sx = 0.f, sy = 0.f, sz = 0.f;
        mass0 = mass1 = mass2 = 0.f;
        #pragma unroll
        for (int j = 0; j < 8; j++) {
            float ov = __shfl_xor_sync(0xffffffffu, v[0],  1);
            int   oi = __shfl_xor_sync(0xffffffffu, ix[0], 1);
            bool take_other = (ov > v[0]) || (ov == v[0] && oi < ix[0]);
            int  wi  = take_other ? oi : ix[0];
            bool won = !take_other;
            #pragma unroll
            for (int u = 0; u < 7; u++) {
                v[u]  = won ? v[u + 1]  : v[u];
                ix[u] = won ? ix[u + 1] : ix[u];
            }
            if (won) { v[7] = -CUDART_INF_F; ix[7] = 0x7fffffff; }

            float4 p = sP[wi];
            sE += p.x; sx += p.y; sy += p.z; sz += p.w;
            if (j == 1) mass0 = mass_from_sum(sE, sx, sy, sz);
            if (j == 3) mass1 = mass_from_sum(sE, sx, sy, sz);
            if (j == 7) mass2 = mass_from_sum(sE, sx, sy, sz);
        }
    } else {
        float mm = sqrtf(1e-8f);  // m2 * 0 -> sqrt(1e-8), as the reference
        mass0 = mass1 = mass2 = mm;
    }

    // h = gelu(mass @ W1 + b1); each of the 2 lanes writes 32 of 64 channels.
    const int m = b * TLEN + t;
    #pragma unroll
    for (int cc = 0; cc < 32; cc++) {
        int c = r * 32 + cc;
        float x = fmaf(mass0, __ldg(&W1[c]),
                  fmaf(mass1, __ldg(&W1[HDIM + c]),
                  fmaf(mass2, __ldg(&W1[2 * HDIM + c]), __ldg(&b1[c]))));
        float g = x * 0.5f * (1.0f + erff(x * 0.70710678118654752f));
        g_h[(size_t)c * MTOT + m] = g;
    }
}

// ---------------------------------------------------------------------------
// Kernel B: out[M,512] = h[M,64] @ W2[64,512] + b2
// 64(M) x 128(N) tile, 128 threads, 8x8 microtile, packed fma.rn.f32x2.
// Shared: As[64][64] (16KB) + Bs[64][128] (32KB) = 48KB -> 4 blocks/SM.
// ---------------------------------------------------------------------------
__global__ __launch_bounds__(128) void mlp2_kernel(
    const float* __restrict__ W2,   // [64,512]
    const float* __restrict__ b2,   // [512]
    float* __restrict__ out)        // [M,512]
{
    __shared__ float As[64][64];
    __shared__ float Bs[64][128];

    const int m0  = blockIdx.x * 64;
    const int n0  = blockIdx.y * 128;
    const int tid = threadIdx.x;

    // A tile: g_h k-major -> coalesced float4 loads. 1024 float4 / 128 threads.
    #pragma unroll
    for (int i = 0; i < 8; i++) {
        int f  = tid + 128 * i;       // 0..1023
        int k  = f >> 4;
        int mq = f & 15;
        *(float4*)&As[k][mq * 4] = *(const float4*)&g_h[(size_t)k * MTOT + m0 + mq * 4];
    }
    // B tile: W2[k][n0 .. n0+127]. 2048 float4 / 128 threads.
    #pragma unroll
    for (int i = 0; i < 16; i++) {
        int f  = tid + 128 * i;       // 0..2047
        int k  = f >> 5;
        int nq = f & 31;
        *(float4*)&Bs[k][nq * 4] = *(const float4*)&W2[k * DDIM + n0 + nq * 4];
    }
    __syncthreads();

    const int rm = (tid & 7) * 8;
    const int rn = (tid >> 3) * 8;

    unsigned long long acc[8][4];
    #pragma unroll
    for (int i = 0; i < 8; i++)
        #pragma unroll
        for (int j = 0; j < 4; j++) acc[i][j] = 0ULL;  // (0.0f, 0.0f)

    #pragma unroll 8
    for (int k = 0; k < 64; k++) {
        float4 a0 = *(float4*)&As[k][rm];
        float4 a1 = *(float4*)&As[k][rm + 4];
        float4 c0 = *(float4*)&Bs[k][rn];
        float4 c1 = *(float4*)&Bs[k][rn + 4];
        unsigned long long bp0 = pk2(c0.x, c0.y);
        unsigned long long bp1 = pk2(c0.z, c0.w);
        unsigned long long bp2 = pk2(c1.x, c1.y);
        unsigned long long bp3 = pk2(c1.z, c1.w);
        float av[8] = {a0.x, a0.y, a0.z, a0.w, a1.x, a1.y, a1.z, a1.w};
        #pragma unroll
        for (int i = 0; i < 8; i++) {
            unsigned long long ad = pk2(av[i], av[i]);
            ffma2(acc[i][0], ad, bp0);
            ffma2(acc[i][1], ad, bp1);
            ffma2(acc[i][2], ad, bp2);
            ffma2(acc[i][3], ad, bp3);
        }
    }

    float4 bias0 = *(const float4*)&b2[n0 + rn];
    float4 bias1 = *(const float4*)&b2[n0 + rn + 4];
    #pragma unroll
    for (int i = 0; i < 8; i++) {
        float x0, y0, x1, y1, x2, y2, x3, y3;
        upk2(acc[i][0], x0, y0);
        upk2(acc[i][1], x1, y1);
        upk2(acc[i][2], x2, y2);
        upk2(acc[i][3], x3, y3);
        float4 o0 = make_float4(x0 + bias0.x, y0 + bias0.y, x1 + bias0.z, y1 + bias0.w);
        float4 o1 = make_float4(x2 + bias1.x, y2 + bias1.y, x3 + bias1.z, y3 + bias1.w);
        float* row = &out[(size_t)(m0 + rm + i) * DDIM + n0 + rn];
        *(float4*)row       = o0;
        *(float4*)(row + 4) = o1;
    }
}

// ---------------------------------------------------------------------------
extern "C" void kernel_launch(void* const* d_in, const int* in_sizes, int n_in,
                              void* d_out, int out_size) {
    const float* tok  = (const float*)d_in[0];   // [16,2048,4]
    const void*  mask = (const void*)d_in[1];    // [16,2048] bool (dtype probed)
    const float* W1   = (const float*)d_in[2];   // [3,64]
    const float* b1   = (const float*)d_in[3];   // [64]
    const float* W2   = (const float*)d_in[4];   // [64,512]
    const float* b2   = (const float*)d_in[5];   // [512]
    float*       out  = (float*)d_out;           // [16,2048,512]

    dim3 gA(TLEN / 128, BATCH);
    mass_h_kernel<<<gA, 256>>>(tok, mask, W1, b1);

    dim3 gB(MTOT / 64, DDIM / 128);
    mlp2_kernel<<<gB, 128>>>(W2, b2, out);
}

// round 6
// speedup vs baseline: 2.3941x; 1.2612x over previous
#include <cuda_runtime.h>
#include <cuda_bf16.h>
#include <math.h>
#include <math_constants.h>
#include <cstdint>

#define BATCH 16
#define TLEN  2048
#define HDIM  64
#define DDIM  512
#define MTOT  (BATCH * TLEN)

// h split into bf16 hi/lo, row-major [M][64] (K-major; 128B rows).
__device__ __nv_bfloat16 g_hh[(size_t)MTOT * HDIM];
__device__ __nv_bfloat16 g_hl[(size_t)MTOT * HDIM];
// W2 split into bf16 hi/lo, [N][K] layout (K contiguous = col-major B for mma).
__device__ __nv_bfloat16 g_whi[DDIM * HDIM];
__device__ __nv_bfloat16 g_wlo[DDIM * HDIM];

__device__ __forceinline__ float mass_from_sum(float sE, float sx, float sy, float sz) {
    float s2 = sx * sx + sy * sy + sz * sz;
    float m2 = sE * sE - s2;
    m2 = fmaxf(m2, 0.0f);
    return sqrtf(m2 + 1e-8f);
}

// ---------------------------------------------------------------------------
// Kernel A: 2 lanes per token; stable private top-8 + pairwise shuffle merge.
// ---------------------------------------------------------------------------
__global__ __launch_bounds__(256) void mass_h_kernel(
    const float* __restrict__ tok,     // [B,T,4]
    const void*  __restrict__ maskp,   // [B,T] bool — dtype probed (u8 / 32-bit)
    const float* __restrict__ W1,      // [3,64]
    const float* __restrict__ b1)      // [64]
{
    __shared__ float4 sP[TLEN];
    __shared__ int sLen;

    const int b   = blockIdx.y;
    const int tid = threadIdx.x;
    if (tid == 0) sLen = 0;
    __syncthreads();

    const unsigned int w0 = *(const unsigned int*)maskp;
    const bool byte_mode = (w0 == 0x01010101u) || (w0 == 0xFFFFFFFFu);

    int cnt = 0;
    #pragma unroll
    for (int s = tid; s < TLEN; s += 256) {
        float4 c = ((const float4*)tok)[b * TLEN + s];
        float E = c.x, Pt = c.y, eta = c.z, phi = c.w;
        float sphi, cphi;
        sincosf(phi, &sphi, &cphi);
        float px = Pt * cphi;
        float py = Pt * sphi;
        eta = fminf(fmaxf(eta, -20.0f), 20.0f);
        float pz = Pt * sinhf(eta);
        sP[s] = make_float4(E, px, py, pz);
        if (byte_mode)
            cnt += (((const unsigned char*)maskp)[b * TLEN + s] != 0) ? 1 : 0;
        else
            cnt += (((const unsigned int*)maskp)[b * TLEN + s] != 0u) ? 1 : 0;
    }
    #pragma unroll
    for (int o = 16; o > 0; o >>= 1) cnt += __shfl_down_sync(0xffffffffu, cnt, o);
    if ((tid & 31) == 0) atomicAdd(&sLen, cnt);
    __syncthreads();

    const int L = sLen;
    const int r = tid & 1;
    const int t = blockIdx.x * 128 + (tid >> 1);

    float mass0, mass1, mass2;

    if (t < L) {
        float4 q = sP[t];
        const float qE = q.x, qx = -q.y, qy = -q.z, qz = -q.w;

        float v[8];
        int   ix[8];
        #pragma unroll
        for (int j = 0; j < 8; j++) { v[j] = -CUDART_INF_F; ix[j] = 0x7fffffff; }

        #pragma unroll 4
        for (int s = r; s < L; s += 2) {
            float4 p = sP[s];
            float d = fmaf(qz, p.w, fmaf(qy, p.z, fmaf(qx, p.y, qE * p.x)));
            if (d > v[7]) {
                float nv = d; int ni = s;
                #pragma unroll
                for (int j = 0; j < 8; j++) {
                    bool sw   = nv > v[j];
                    float hi  = fmaxf(nv, v[j]);
                    float lo  = fminf(nv, v[j]);
                    int hidx  = sw ? ni    : ix[j];
                    int lidx  = sw ? ix[j] : ni;
                    v[j] = hi; ix[j] = hidx;
                    nv   = lo; ni    = lidx;
                }
            }
        }

        float sE = 0.f, sx = 0.f, sy = 0.f, sz = 0.f;
        mass0 = mass1 = mass2 = 0.f;
        #pragma unroll
        for (int j = 0; j < 8; j++) {
            float ov = __shfl_xor_sync(0xffffffffu, v[0],  1);
            int   oi = __shfl_xor_sync(0xffffffffu, ix[0], 1);
            bool take_other = (ov > v[0]) || (ov == v[0] && oi < ix[0]);
            int  wi  = take_other ? oi : ix[0];
            bool won = !take_other;
            #pragma unroll
            for (int u = 0; u < 7; u++) {
                v[u]  = won ? v[u + 1]  : v[u];
                ix[u] = won ? ix[u + 1] : ix[u];
            }
            if (won) { v[7] = -CUDART_INF_F; ix[7] = 0x7fffffff; }

            float4 p = sP[wi];
            sE += p.x; sx += p.y; sy += p.z; sz += p.w;
            if (j == 1) mass0 = mass_from_sum(sE, sx, sy, sz);
            if (j == 3) mass1 = mass_from_sum(sE, sx, sy, sz);
            if (j == 7) mass2 = mass_from_sum(sE, sx, sy, sz);
        }
    } else {
        float mm = sqrtf(1e-8f);
        mass0 = mass1 = mass2 = mm;
    }

    // h = gelu(mass @ W1 + b1), stored as bf16 hi/lo split, row-major [m][c].
    const size_t m = (size_t)b * TLEN + t;
    #pragma unroll
    for (int cc = 0; cc < 32; cc += 2) {
        int c = r * 32 + cc;
        float g2[2];
        #pragma unroll
        for (int u = 0; u < 2; u++) {
            float x = fmaf(mass0, __ldg(&W1[c + u]),
                      fmaf(mass1, __ldg(&W1[HDIM + c + u]),
                      fmaf(mass2, __ldg(&W1[2 * HDIM + c + u]), __ldg(&b1[c + u]))));
            g2[u] = x * 0.5f * (1.0f + erff(x * 0.70710678118654752f));
        }
        __nv_bfloat16 h0 = __float2bfloat16(g2[0]);
        __nv_bfloat16 h1 = __float2bfloat16(g2[1]);
        __nv_bfloat16 l0 = __float2bfloat16(g2[0] - __bfloat162float(h0));
        __nv_bfloat16 l1 = __float2bfloat16(g2[1] - __bfloat162float(h1));
        *(__nv_bfloat162*)&g_hh[m * HDIM + c] = __nv_bfloat162(h0, h1);
        *(__nv_bfloat162*)&g_hl[m * HDIM + c] = __nv_bfloat162(l0, l1);
    }
}

// ---------------------------------------------------------------------------
// W2 split kernel: g_whi/g_wlo[n*64+k] = bf16 hi/lo of W2[k*512+n]
// ---------------------------------------------------------------------------
__global__ __launch_bounds__(256) void w2cvt_kernel(const float* __restrict__ W2) {
    int idx = blockIdx.x * 256 + threadIdx.x;   // 0 .. 32767
    int n = idx >> 6;
    int k = idx & 63;
    float w = W2[k * DDIM + n];
    __nv_bfloat16 hi = __float2bfloat16(w);
    float lo = w - __bfloat162float(hi);
    g_whi[idx] = hi;
    g_wlo[idx] = __float2bfloat16(lo);
}

// ---------------------------------------------------------------------------
// mma.sync GEMM: out[M,512] = (hh+hl)[M,64] @ (Whi+Wlo)^T + b2
// 3 bf16 products: Ah*Bh + Ah*Bl + Al*Bh (compensated, err ~3e-5).
// CTA: 128M x 128N, 256 threads (8 warps, warp = 32M x 64N), K=64.
// smem: Ah/Al/Bh/Bl [128][64] bf16, SW128-swizzled, 64KB dynamic.
// ---------------------------------------------------------------------------
#define SW128(o) ((o) ^ (((o) >> 3) & 0x70))
#define GSM_AH 0
#define GSM_AL 16384
#define GSM_BH 32768
#define GSM_BL 49152
#define GSM_TOT 65536

__device__ __forceinline__ uint32_t smem_u32(const void* p) {
    uint32_t a;
    asm("{ .reg .u64 t; cvta.to.shared.u64 t, %1; cvt.u32.u64 %0, t; }" : "=r"(a) : "l"(p));
    return a;
}
__device__ __forceinline__ void ldmx4(uint32_t* r, uint32_t addr) {
    asm volatile("ldmatrix.sync.aligned.m8n8.x4.shared.b16 {%0,%1,%2,%3}, [%4];"
        : "=r"(r[0]), "=r"(r[1]), "=r"(r[2]), "=r"(r[3]) : "r"(addr));
}
__device__ __forceinline__ void mma16816(float* c, const uint32_t* a, const uint32_t* b) {
    asm volatile("mma.sync.aligned.m16n8k16.row.col.f32.bf16.bf16.f32 "
        "{%0,%1,%2,%3}, {%4,%5,%6,%7}, {%8,%9}, {%0,%1,%2,%3};"
        : "+f"(c[0]), "+f"(c[1]), "+f"(c[2]), "+f"(c[3])
        : "r"(a[0]), "r"(a[1]), "r"(a[2]), "r"(a[3]), "r"(b[0]), "r"(b[1]));
}

__global__ __launch_bounds__(256) void gemm_mma_kernel(
    const float* __restrict__ b2,   // [512]
    float* __restrict__ out)        // [M,512]
{
    extern __shared__ __align__(1024) char smem[];
    const uint32_t sbase = smem_u32(smem);
    const int tid  = threadIdx.x;
    const int wid  = tid >> 5;
    const int lane = tid & 31;
    const int m0   = blockIdx.x * 128;
    const int n0   = blockIdx.y * 128;

    // Load tiles (uint4 chunks, SW128 swizzle). 1024 chunks per array / 256 thr.
    #pragma unroll
    for (int i = 0; i < 4; i++) {
        int f  = tid + 256 * i;
        int rr = f >> 3;
        int qq = f & 7;
        uint32_t off = SW128((uint32_t)(rr * 128 + qq * 16));
        *(uint4*)(smem + GSM_AH + off) = *(const uint4*)(g_hh  + (size_t)(m0 + rr) * HDIM + qq * 8);
        *(uint4*)(smem + GSM_AL + off) = *(const uint4*)(g_hl  + (size_t)(m0 + rr) * HDIM + qq * 8);
        *(uint4*)(smem + GSM_BH + off) = *(const uint4*)(g_whi + (size_t)(n0 + rr) * HDIM + qq * 8);
        *(uint4*)(smem + GSM_BL + off) = *(const uint4*)(g_wlo + (size_t)(n0 + rr) * HDIM + qq * 8);
    }
    __syncthreads();

    const int wm = (wid & 3) * 32;   // warp m offset (0,32,64,96)
    const int wn = (wid >> 2) * 64;  // warp n offset (0,64)

    float acc[2][8][4];
    #pragma unroll
    for (int mt = 0; mt < 2; mt++)
        #pragma unroll
        for (int nt = 0; nt < 8; nt++)
            #pragma unroll
            for (int u = 0; u < 4; u++) acc[mt][nt][u] = 0.0f;

    // A ldmatrix address pattern: lane -> row = base + (lane%16), khalf = lane/16
    const int a_row_l = lane & 15;
    const int a_kb_l  = (lane >> 4) * 16;
    // B ldmatrix x4 (2 n-tiles): lane -> n = base + (lane/16)*8 + (lane%8), khalf = (lane/8)&1
    const int b_n_l  = ((lane >> 4) << 3) + (lane & 7);
    const int b_kb_l = ((lane >> 3) & 1) * 16;

    #pragma unroll
    for (int ks = 0; ks < 4; ks++) {
        uint32_t ah[2][4], al[2][4];
        #pragma unroll
        for (int mt = 0; mt < 2; mt++) {
            uint32_t off = SW128((uint32_t)((wm + mt * 16 + a_row_l) * 128 + ks * 32 + a_kb_l));
            ldmx4(ah[mt], sbase + GSM_AH + off);
            ldmx4(al[mt], sbase + GSM_AL + off);
        }
        #pragma unroll
        for (int np = 0; np < 4; np++) {
            uint32_t bh[4], bl[4];
            uint32_t off = SW128((uint32_t)((wn + np * 16 + b_n_l) * 128 + ks * 32 + b_kb_l));
            ldmx4(bh, sbase + GSM_BH + off);
            ldmx4(bl, sbase + GSM_BL + off);
            #pragma unroll
            for (int mt = 0; mt < 2; mt++) {
                mma16816(acc[mt][2 * np],     ah[mt], bh);
                mma16816(acc[mt][2 * np],     ah[mt], bl);
                mma16816(acc[mt][2 * np],     al[mt], bh);
                mma16816(acc[mt][2 * np + 1], ah[mt], bh + 2);
                mma16816(acc[mt][2 * np + 1], ah[mt], bl + 2);
                mma16816(acc[mt][2 * np + 1], al[mt], bh + 2);
            }
        }
    }

    // Epilogue: c-frag lane mapping: c0,c1 -> row lane/4, cols 2(lane%4)+{0,1};
    // c2,c3 -> row lane/4 + 8. Add bias, store float2.
    const int er = lane >> 2;
    const int ec = (lane & 3) * 2;
    #pragma unroll
    for (int mt = 0; mt < 2; mt++) {
        #pragma unroll
        for (int nt = 0; nt < 8; nt++) {
            int n = n0 + wn + nt * 8 + ec;
            float bx = __ldg(&b2[n]);
            float by = __ldg(&b2[n + 1]);
            int row0 = m0 + wm + mt * 16 + er;
            float2 o0 = make_float2(acc[mt][nt][0] + bx, acc[mt][nt][1] + by);
            float2 o1 = make_float2(acc[mt][nt][2] + bx, acc[mt][nt][3] + by);
            *(float2*)&out[(size_t)row0 * DDIM + n]       = o0;
            *(float2*)&out[(size_t)(row0 + 8) * DDIM + n] = o1;
        }
    }
}

// ---------------------------------------------------------------------------
extern "C" void kernel_launch(void* const* d_in, const int* in_sizes, int n_in,
                              void* d_out, int out_size) {
    const float* tok  = (const float*)d_in[0];   // [16,2048,4]
    const void*  mask = (const void*)d_in[1];    // [16,2048] bool (dtype probed)
    const float* W1   = (const float*)d_in[2];   // [3,64]
    const float* b1   = (const float*)d_in[3];   // [64]
    const float* W2   = (const float*)d_in[4];   // [64,512]
    const float* b2   = (const float*)d_in[5];   // [512]
    float*       out  = (float*)d_out;           // [16,2048,512]

    static bool attr_done = false;
    if (!attr_done) {
        cudaFuncSetAttribute(gemm_mma_kernel, cudaFuncAttributeMaxDynamicSharedMemorySize, GSM_TOT);
        attr_done = true;
    }

    dim3 gA(TLEN / 128, BATCH);
    mass_h_kernel<<<gA, 256>>>(tok, mask, W1, b1);

    w2cvt_kernel<<<(DDIM * HDIM) / 256, 256>>>(W2);

    dim3 gG(MTOT / 128, DDIM / 128);
    gemm_mma_kernel<<<gG, 256, GSM_TOT>>>(b2, out);
}